// round 14
// baseline (speedup 1.0000x reference)
#include <cuda_runtime.h>
#include <math.h>

#define NN 50000
#define EE 800000
#define D  64
#define GG 64
#define BN_EPS 1e-5f
#define SCAN_BLOCKS 196   // ceil(50000/256)

// ---------------- device scratch (device-code access only) ----------------
__device__ int   g_degi  [NN];          // zero at load; re-zeroed by scan23 each call
__device__ float g_dinv  [NN];
__device__ int   g_rowptr[NN + 1];
__device__ int   g_cursor[NN];
__device__ int   g_blocksum[256];
__device__ __align__(16) int2  g_csr[EE + NN];  // (src, dinv[src] bits), even-padded
__device__ __align__(16) float g_h1 [NN * D];
__device__ __align__(16) float g_agg[NN * D];
__device__ __align__(16) float g_h2 [NN * D];
__device__ float g_bnsum[D];
__device__ float g_bnsq [D];
__device__ __align__(16) float g_pool[GG * D];
__device__ float g_cnt [GG];

// ---------------- packed f32x2 helpers (aggregate inner loop only) ----------------
__device__ __forceinline__ unsigned long long pack2(float x, float y) {
    unsigned long long r;
    asm("mov.b64 %0, {%1, %2};" : "=l"(r) : "f"(x), "f"(y));
    return r;
}
__device__ __forceinline__ void ffma2(unsigned long long& d,
                                      unsigned long long a, unsigned long long b) {
    asm("fma.rn.f32x2 %0, %1, %2, %0;" : "+l"(d) : "l"(a), "l"(b));
}
__device__ __forceinline__ float2 unpack2(unsigned long long v) {
    float2 f;
    asm("mov.b64 {%0, %1}, %2;" : "=f"(f.x), "=f"(f.y) : "l"(v));
    return f;
}

// ---------------- zero small accumulators (runs on side stream) ----------------
__global__ void zero_kernel() {
    int i = blockIdx.x * blockDim.x + threadIdx.x;
    if (i < GG * D) g_pool[i] = 0.f;
    if (i < D)    { g_bnsum[i] = 0.f; g_bnsq[i] = 0.f; }
    if (i < GG)     g_cnt[i] = 0.f;
}

// ---------------- graph-node counts from batch (side stream, off critical path) ------
__global__ void cnt_kernel(const int* __restrict__ batch) {
    int i = blockIdx.x * blockDim.x + threadIdx.x;
    if (i < NN) atomicAdd(&g_cnt[batch[i]], 1.0f);
}

// ---------------- degree: 4 edges per thread ----------------
__global__ void degree_kernel(const int* __restrict__ dst) {
    int t = blockIdx.x * blockDim.x + threadIdx.x;
    if (t * 4 >= EE) return;
    int4 d4 = ((const int4*)dst)[t];
    atomicAdd(&g_degi[d4.x], 1);
    atomicAdd(&g_degi[d4.y], 1);
    atomicAdd(&g_degi[d4.z], 1);
    atomicAdd(&g_degi[d4.w], 1);
}

// ---------------- scan phase 1: padded block sums (+ fused dinv) ----------------
__global__ void scan1_kernel() {
    __shared__ int s[256];
    int idx = blockIdx.x * 256 + threadIdx.x;
    int dv = (idx < NN) ? g_degi[idx] : 0;
    if (idx < NN) g_dinv[idx] = rsqrtf((float)dv + 1.0f);
    s[threadIdx.x] = (dv + 1) & ~1;               // pad degree to even
    __syncthreads();
    for (int o = 128; o > 0; o >>= 1) {
        if (threadIdx.x < o) s[threadIdx.x] += s[threadIdx.x + o];
        __syncthreads();
    }
    if (threadIdx.x == 0) g_blocksum[blockIdx.x] = s[0];
}

// ---------------- scan 2+3 fused: rowptr/cursor, pad slot, degi reset ----------------
__global__ void scan23_kernel() {
    __shared__ int sb[256];
    __shared__ int s[256];
    int t = threadIdx.x;
    sb[t] = (t < SCAN_BLOCKS) ? g_blocksum[t] : 0;
    __syncthreads();
    for (int o = 1; o < 256; o <<= 1) {
        int a = (t >= o) ? sb[t - o] : 0;
        __syncthreads();
        sb[t] += a;
        __syncthreads();
    }
    int blockoff = (blockIdx.x == 0) ? 0 : sb[blockIdx.x - 1];
    int idx = blockIdx.x * 256 + t;
    int v  = (idx < NN) ? g_degi[idx] : 0;
    int vp = (v + 1) & ~1;
    s[t] = vp;
    __syncthreads();
    for (int o = 1; o < 256; o <<= 1) {
        int a = (t >= o) ? s[t - o] : 0;
        __syncthreads();
        s[t] += a;
        __syncthreads();
    }
    if (idx < NN) {
        int rp = blockoff + s[t] - vp;
        g_rowptr[idx] = rp;
        g_cursor[idx] = rp;
        if (v & 1) g_csr[rp + v] = make_int2(0, 0);  // zero pad entry
        g_degi[idx] = 0;                             // invariant for next call
        if (idx == NN - 1) g_rowptr[NN] = blockoff + s[t];
    }
}

// ---------------- CSR fill: 4 edges/thread, stores (src, dinv[src]) ----------------
__global__ void csr_fill_kernel(const int* __restrict__ src,
                                const int* __restrict__ dst) {
    int t = blockIdx.x * blockDim.x + threadIdx.x;
    if (t * 4 >= EE) return;
    int4 s4 = ((const int4*)src)[t];
    int4 d4 = ((const int4*)dst)[t];
    int p0 = atomicAdd(&g_cursor[d4.x], 1);
    int p1 = atomicAdd(&g_cursor[d4.y], 1);
    int p2 = atomicAdd(&g_cursor[d4.z], 1);
    int p3 = atomicAdd(&g_cursor[d4.w], 1);
    g_csr[p0] = make_int2(s4.x, __float_as_int(g_dinv[s4.x]));
    g_csr[p1] = make_int2(s4.y, __float_as_int(g_dinv[s4.y]));
    g_csr[p2] = make_int2(s4.z, __float_as_int(g_dinv[s4.z]));
    g_csr[p3] = make_int2(s4.w, __float_as_int(g_dinv[s4.w]));
}

// ---------------- GEMM: R8 proven shape (256 threads, scalar FFMA) ----------------
template<int MODE>
__global__ void gemm64_kernel(const float* __restrict__ Xp,
                              const float* __restrict__ W,
                              const float* __restrict__ gamma,
                              const float* __restrict__ beta) {
    const float* __restrict__ X = (MODE == 0) ? Xp : (const float*)g_agg;
    float* __restrict__       Y = (MODE == 0) ? g_h1 : g_h2;

    __shared__ float sX[64][65];
    __shared__ __align__(16) float sW[64][64];
    __shared__ float s_scale[64], s_shift[64];

    int tid  = threadIdx.y * 16 + threadIdx.x;
    int row0 = blockIdx.x * 64;

    if (MODE == 1) {
        if (tid < 64) {
            float inv_n = 1.0f / (float)NN;
            float mu  = g_bnsum[tid] * inv_n;
            float var = g_bnsq[tid] * inv_n - mu * mu;
            float sc  = gamma[tid] * rsqrtf(var + BN_EPS);
            s_scale[tid] = sc;
            s_shift[tid] = beta[tid] - mu * sc;
        }
        __syncthreads();
    }

    #pragma unroll
    for (int t = tid * 4; t < 4096; t += 1024) {
        *(float4*)(&sW[t >> 6][t & 63]) = *(const float4*)(W + t);
    }
    #pragma unroll
    for (int t = tid * 4; t < 4096; t += 1024) {
        int r = t >> 6, c = t & 63;
        float4 v = make_float4(0.f, 0.f, 0.f, 0.f);
        if (row0 + r < NN) v = *(const float4*)(X + (size_t)(row0 + r) * D + c);
        if (MODE == 1) {
            v.x = v.x * s_scale[c]     + s_shift[c];
            v.y = v.y * s_scale[c + 1] + s_shift[c + 1];
            v.z = v.z * s_scale[c + 2] + s_shift[c + 2];
            v.w = v.w * s_scale[c + 3] + s_shift[c + 3];
            v.x = (v.x > 0.f) ? v.x : (__expf(v.x) - 1.0f);
            v.y = (v.y > 0.f) ? v.y : (__expf(v.y) - 1.0f);
            v.z = (v.z > 0.f) ? v.z : (__expf(v.z) - 1.0f);
            v.w = (v.w > 0.f) ? v.w : (__expf(v.w) - 1.0f);
        }
        sX[r][c] = v.x; sX[r][c + 1] = v.y; sX[r][c + 2] = v.z; sX[r][c + 3] = v.w;
    }
    __syncthreads();

    float acc[4][4] = {};
    int c0 = threadIdx.x * 4, r0 = threadIdx.y * 4;
    #pragma unroll 16
    for (int k = 0; k < 64; k++) {
        float4 w = *(const float4*)(&sW[k][c0]);
        #pragma unroll
        for (int r = 0; r < 4; r++) {
            float xv = sX[r0 + r][k];
            acc[r][0] += xv * w.x; acc[r][1] += xv * w.y;
            acc[r][2] += xv * w.z; acc[r][3] += xv * w.w;
        }
    }
    #pragma unroll
    for (int r = 0; r < 4; r++) {
        int row = row0 + r0 + r;
        if (row < NN)
            *(float4*)(Y + (size_t)row * D + c0) =
                make_float4(acc[r][0], acc[r][1], acc[r][2], acc[r][3]);
    }
}

// ---------------- gather aggregation: warp/node, half-warps (R8 exact) ----------------
// MODE 0: h=g_h1 -> g_agg (no atomics).  MODE 1: h=g_h2 -> outp + pool atomics.
template<int MODE>
__global__ void aggregate_kernel(float* __restrict__ outp,
                                 const float* __restrict__ bias,
                                 const int* __restrict__ batch) {
    const float* __restrict__ h = (MODE == 0) ? g_h1 : g_h2;
    float* __restrict__ dstbuf  = (MODE == 0) ? g_agg : outp;

    int n    = (blockIdx.x * blockDim.x + threadIdx.x) >> 5;  // grid: n < NN
    int lane = threadIdx.x & 31;
    int half = lane >> 4;
    int fl   = lane & 15;

    int e0 = g_rowptr[n];
    int e1 = g_rowptr[n + 1];     // padded even length

    unsigned long long a0 = 0ull, a1 = 0ull;
    #pragma unroll 4
    for (int e = e0 + half; e < e1; e += 2) {
        int2 ec = g_csr[e];
        float c = __int_as_float(ec.y);             // dinv[src]
        float4 v = ((const float4*)h)[(size_t)ec.x * 16 + fl];
        unsigned long long cc = pack2(c, c);
        ffma2(a0, cc, pack2(v.x, v.y));
        ffma2(a1, cc, pack2(v.z, v.w));
    }
    float2 f0 = unpack2(a0), f1 = unpack2(a1);
    float4 acc = make_float4(f0.x, f0.y, f1.x, f1.y);
    acc.x += __shfl_xor_sync(0xffffffffu, acc.x, 16);
    acc.y += __shfl_xor_sync(0xffffffffu, acc.y, 16);
    acc.z += __shfl_xor_sync(0xffffffffu, acc.z, 16);
    acc.w += __shfl_xor_sync(0xffffffffu, acc.w, 16);

    float di = g_dinv[n];
    float cs = di * di;
    if (half == 0) {
        float4 hv = ((const float4*)h)[(size_t)n * 16 + fl];
        float4 bv = ((const float4*)bias)[fl];
        acc.x = fmaf(di, acc.x, fmaf(cs, hv.x, bv.x));
        acc.y = fmaf(di, acc.y, fmaf(cs, hv.y, bv.y));
        acc.z = fmaf(di, acc.z, fmaf(cs, hv.z, bv.z));
        acc.w = fmaf(di, acc.w, fmaf(cs, hv.w, bv.w));
        ((float4*)dstbuf)[(size_t)n * 16 + fl] = acc;

        if (MODE == 1) {
            int g = batch[n];
            atomicAdd(((float4*)g_pool) + (size_t)g * 16 + fl, acc);
        }
    }
}

// ---------------- BN statistics: one streaming pass over g_agg ----------------
__global__ void bnstats_kernel() {
    int tid    = blockIdx.x * blockDim.x + threadIdx.x;
    int stride = gridDim.x * blockDim.x;
    float sum = 0.f, sq = 0.f;
    for (int idx = tid; idx < NN * D; idx += stride) {
        float v = g_agg[idx];
        sum += v; sq += v * v;
    }
    __shared__ float s_sum[256], s_sq[256];
    s_sum[threadIdx.x] = sum; s_sq[threadIdx.x] = sq;
    __syncthreads();
    if (threadIdx.x < 64) {
        float ts = s_sum[threadIdx.x] + s_sum[threadIdx.x + 64] +
                   s_sum[threadIdx.x + 128] + s_sum[threadIdx.x + 192];
        float tq = s_sq[threadIdx.x] + s_sq[threadIdx.x + 64] +
                   s_sq[threadIdx.x + 128] + s_sq[threadIdx.x + 192];
        atomicAdd(&g_bnsum[threadIdx.x], ts);
        atomicAdd(&g_bnsq [threadIdx.x], tq);
    }
}

__global__ void pool_div_kernel(float* __restrict__ rep) {
    int t = blockIdx.x * blockDim.x + threadIdx.x;
    if (t >= GG * D) return;
    int g = t >> 6;
    rep[t] = g_pool[t] / fmaxf(g_cnt[g], 1.0f);
}

// ---------------- side stream for capture-time fork/join ----------------
struct SideCtx {
    cudaStream_t s2;
    cudaEvent_t evFork, evJoin;
    SideCtx() {
        cudaStreamCreateWithFlags(&s2, cudaStreamNonBlocking);
        cudaEventCreateWithFlags(&evFork, cudaEventDisableTiming);
        cudaEventCreateWithFlags(&evJoin, cudaEventDisableTiming);
    }
};
static SideCtx g_side;

// ---------------- launch ----------------
extern "C" void kernel_launch(void* const* d_in, const int* in_sizes, int n_in,
                              void* d_out, int out_size) {
    const float* x     = (const float*)d_in[0];
    const int*   ei    = (const int*)  d_in[1];
    const int*   batch = (const int*)  d_in[2];
    const float* W1    = (const float*)d_in[3];
    const float* b1    = (const float*)d_in[4];
    const float* gamma = (const float*)d_in[5];
    const float* beta  = (const float*)d_in[6];
    const float* W2    = (const float*)d_in[7];
    const float* b2    = (const float*)d_in[8];
    float* out = (float*)d_out;
    const int* src = ei;
    const int* dst = ei + EE;

    const int TPB = 256;
    int e4_blocks   = (EE / 4 + TPB - 1) / TPB;        // 782
    int gemm_blocks = (NN + 63) / 64;                  // 782
    int agg_blocks  = NN / 8;                          // 6250 (warp per node)
    int node_blocks = (NN + TPB - 1) / TPB;            // 196

    // Fork: zero + graph counts + GEMM-1 run concurrently with the CSR build.
    cudaEventRecord(g_side.evFork, 0);
    cudaStreamWaitEvent(g_side.s2, g_side.evFork, 0);
    zero_kernel<<<16, TPB, 0, g_side.s2>>>();
    cnt_kernel<<<node_blocks, TPB, 0, g_side.s2>>>(batch);
    gemm64_kernel<0><<<gemm_blocks, dim3(16, 16), 0, g_side.s2>>>(x, W1, gamma, beta);
    cudaEventRecord(g_side.evJoin, g_side.s2);

    // Main branch: CSR build (g_degi is zero on entry — invariant)
    degree_kernel<<<e4_blocks, TPB>>>(dst);
    scan1_kernel<<<SCAN_BLOCKS, 256>>>();
    scan23_kernel<<<SCAN_BLOCKS, 256>>>();
    csr_fill_kernel<<<e4_blocks, TPB>>>(src, dst);

    // Join, then the serial tail (R8 exact)
    cudaStreamWaitEvent(0, g_side.evJoin, 0);
    aggregate_kernel<0><<<agg_blocks, TPB>>>(out, b1, batch);
    bnstats_kernel<<<1184, TPB>>>();
    gemm64_kernel<1><<<gemm_blocks, dim3(16, 16)>>>(x, W2, gamma, beta);
    aggregate_kernel<1><<<agg_blocks, TPB>>>(out, b2, batch);
    pool_div_kernel<<<16, TPB>>>(out + (size_t)NN * D);
}

// round 15
// speedup vs baseline: 1.0717x; 1.0717x over previous
#include <cuda_runtime.h>
#include <math.h>

#define NN 50000
#define EE 800000
#define D  64
#define GG 64
#define BN_EPS 1e-5f
#define SCAN_BLOCKS 196   // ceil(50000/256)

// ---------------- device scratch (device-code access only) ----------------
__device__ int   g_degi  [NN];          // zero at load; re-zeroed by scan23 each call
__device__ float g_dinv  [NN];
__device__ int   g_rowptr[NN + 1];      // padded-exclusive scan + sentinel
__device__ int   g_cursor[NN];
__device__ int   g_blocksum[256];
__device__ __align__(16) int2  g_csr[EE + NN];  // (src, dinv[src] bits), even-padded
__device__ __align__(16) float g_h1 [NN * D];
__device__ __align__(16) float g_agg[NN * D];
__device__ __align__(16) float g_h2 [NN * D];
__device__ float g_bnsum[D];
__device__ float g_bnsq [D];
__device__ __align__(16) float g_pool[GG * D];
__device__ float g_cnt [GG];

// ---------------- packed f32x2 helpers ----------------
__device__ __forceinline__ unsigned long long pack2(float x, float y) {
    unsigned long long r;
    asm("mov.b64 %0, {%1, %2};" : "=l"(r) : "f"(x), "f"(y));
    return r;
}
__device__ __forceinline__ void ffma2(unsigned long long& d,
                                      unsigned long long a, unsigned long long b) {
    asm("fma.rn.f32x2 %0, %1, %2, %0;" : "+l"(d) : "l"(a), "l"(b));
}
__device__ __forceinline__ float2 unpack2(unsigned long long v) {
    float2 f;
    asm("mov.b64 {%0, %1}, %2;" : "=f"(f.x), "=f"(f.y) : "l"(v));
    return f;
}

// ---------------- zero small accumulators (runs on side stream) ----------------
__global__ void zero_kernel() {
    int i = blockIdx.x * blockDim.x + threadIdx.x;
    if (i < GG * D) g_pool[i] = 0.f;
    if (i < D)    { g_bnsum[i] = 0.f; g_bnsq[i] = 0.f; }
    if (i < GG)     g_cnt[i] = 0.f;
}

// ---------------- degree: 4 edges per thread ----------------
__global__ void degree_kernel(const int* __restrict__ dst) {
    int t = blockIdx.x * blockDim.x + threadIdx.x;
    if (t * 4 >= EE) return;
    int4 d4 = ((const int4*)dst)[t];
    atomicAdd(&g_degi[d4.x], 1);
    atomicAdd(&g_degi[d4.y], 1);
    atomicAdd(&g_degi[d4.z], 1);
    atomicAdd(&g_degi[d4.w], 1);
}

// ---------------- scan phase 1: padded block sums (+ fused dinv) ----------------
__global__ void scan1_kernel() {
    __shared__ int s[256];
    int idx = blockIdx.x * 256 + threadIdx.x;
    int dv = (idx < NN) ? g_degi[idx] : 0;
    if (idx < NN) g_dinv[idx] = rsqrtf((float)dv + 1.0f);
    s[threadIdx.x] = (dv + 1) & ~1;               // pad degree to even
    __syncthreads();
    for (int o = 128; o > 0; o >>= 1) {
        if (threadIdx.x < o) s[threadIdx.x] += s[threadIdx.x + o];
        __syncthreads();
    }
    if (threadIdx.x == 0) g_blocksum[blockIdx.x] = s[0];
}

// ---------------- scan 2+3 fused: rowptr/cursor, pad slot, degi reset ----------------
__global__ void scan23_kernel() {
    __shared__ int sb[256];
    __shared__ int s[256];
    int t = threadIdx.x;
    sb[t] = (t < SCAN_BLOCKS) ? g_blocksum[t] : 0;
    __syncthreads();
    for (int o = 1; o < 256; o <<= 1) {
        int a = (t >= o) ? sb[t - o] : 0;
        __syncthreads();
        sb[t] += a;
        __syncthreads();
    }
    int blockoff = (blockIdx.x == 0) ? 0 : sb[blockIdx.x - 1];
    int idx = blockIdx.x * 256 + t;
    int v  = (idx < NN) ? g_degi[idx] : 0;
    int vp = (v + 1) & ~1;
    s[t] = vp;
    __syncthreads();
    for (int o = 1; o < 256; o <<= 1) {
        int a = (t >= o) ? s[t - o] : 0;
        __syncthreads();
        s[t] += a;
        __syncthreads();
    }
    if (idx < NN) {
        int rp = blockoff + s[t] - vp;
        g_rowptr[idx] = rp;
        g_cursor[idx] = rp;
        if (v & 1) g_csr[rp + v] = make_int2(0, 0);  // zero pad entry
        g_degi[idx] = 0;                             // invariant for next call
        if (idx == NN - 1) g_rowptr[NN] = blockoff + s[t];
    }
}

// ---------------- CSR fill: 4 edges/thread, stores (src, dinv[src]) ----------------
__global__ void csr_fill_kernel(const int* __restrict__ src,
                                const int* __restrict__ dst) {
    int t = blockIdx.x * blockDim.x + threadIdx.x;
    if (t * 4 >= EE) return;
    int4 s4 = ((const int4*)src)[t];
    int4 d4 = ((const int4*)dst)[t];
    int p0 = atomicAdd(&g_cursor[d4.x], 1);
    int p1 = atomicAdd(&g_cursor[d4.y], 1);
    int p2 = atomicAdd(&g_cursor[d4.z], 1);
    int p3 = atomicAdd(&g_cursor[d4.w], 1);
    g_csr[p0] = make_int2(s4.x, __float_as_int(g_dinv[s4.x]));
    g_csr[p1] = make_int2(s4.y, __float_as_int(g_dinv[s4.y]));
    g_csr[p2] = make_int2(s4.z, __float_as_int(g_dinv[s4.z]));
    g_csr[p3] = make_int2(s4.w, __float_as_int(g_dinv[s4.w]));
}

// ---------------- GEMM: 256 threads, 4x4 outputs/thread, scalar FFMA ----------------
template<int MODE>
__global__ void gemm64_kernel(const float* __restrict__ Xp,
                              const float* __restrict__ W,
                              const float* __restrict__ gamma,
                              const float* __restrict__ beta) {
    const float* __restrict__ X = (MODE == 0) ? Xp : (const float*)g_agg;
    float* __restrict__       Y = (MODE == 0) ? g_h1 : g_h2;

    __shared__ float sX[64][65];
    __shared__ __align__(16) float sW[64][64];
    __shared__ float s_scale[64], s_shift[64];

    int tid  = threadIdx.y * 16 + threadIdx.x;
    int row0 = blockIdx.x * 64;

    if (MODE == 1) {
        if (tid < 64) {
            float inv_n = 1.0f / (float)NN;
            float mu  = g_bnsum[tid] * inv_n;
            float var = g_bnsq[tid] * inv_n - mu * mu;
            float sc  = gamma[tid] * rsqrtf(var + BN_EPS);
            s_scale[tid] = sc;
            s_shift[tid] = beta[tid] - mu * sc;
        }
        __syncthreads();
    }

    #pragma unroll
    for (int t = tid * 4; t < 4096; t += 1024) {
        *(float4*)(&sW[t >> 6][t & 63]) = *(const float4*)(W + t);
    }
    #pragma unroll
    for (int t = tid * 4; t < 4096; t += 1024) {
        int r = t >> 6, c = t & 63;
        float4 v = make_float4(0.f, 0.f, 0.f, 0.f);
        if (row0 + r < NN) v = *(const float4*)(X + (size_t)(row0 + r) * D + c);
        if (MODE == 1) {
            v.x = v.x * s_scale[c]     + s_shift[c];
            v.y = v.y * s_scale[c + 1] + s_shift[c + 1];
            v.z = v.z * s_scale[c + 2] + s_shift[c + 2];
            v.w = v.w * s_scale[c + 3] + s_shift[c + 3];
            v.x = (v.x > 0.f) ? v.x : (__expf(v.x) - 1.0f);
            v.y = (v.y > 0.f) ? v.y : (__expf(v.y) - 1.0f);
            v.z = (v.z > 0.f) ? v.z : (__expf(v.z) - 1.0f);
            v.w = (v.w > 0.f) ? v.w : (__expf(v.w) - 1.0f);
        }
        sX[r][c] = v.x; sX[r][c + 1] = v.y; sX[r][c + 2] = v.z; sX[r][c + 3] = v.w;
    }
    __syncthreads();

    float acc[4][4] = {};
    int c0 = threadIdx.x * 4, r0 = threadIdx.y * 4;
    #pragma unroll 16
    for (int k = 0; k < 64; k++) {
        float4 w = *(const float4*)(&sW[k][c0]);
        #pragma unroll
        for (int r = 0; r < 4; r++) {
            float xv = sX[r0 + r][k];
            acc[r][0] += xv * w.x; acc[r][1] += xv * w.y;
            acc[r][2] += xv * w.z; acc[r][3] += xv * w.w;
        }
    }
    #pragma unroll
    for (int r = 0; r < 4; r++) {
        int row = row0 + r0 + r;
        if (row < NN)
            *(float4*)(Y + (size_t)row * D + c0) =
                make_float4(acc[r][0], acc[r][1], acc[r][2], acc[r][3]);
    }
}

// ---------------- gather aggregation: warp/node, half-warps (R8 proven layout) -------
// CSR stores dinv[src]; final scale by dinv[n]. NO atomics/syncthreads in MODE 0.
template<int MODE>
__global__ void aggregate_kernel(float* __restrict__ outp,
                                 const float* __restrict__ bias,
                                 const int* __restrict__ batch) {
    const float* __restrict__ h = (MODE == 0) ? g_h1 : g_h2;
    float* __restrict__ dstbuf  = (MODE == 0) ? g_agg : outp;

    int n    = (blockIdx.x * blockDim.x + threadIdx.x) >> 5;  // grid: n < NN
    int lane = threadIdx.x & 31;
    int half = lane >> 4;
    int fl   = lane & 15;

    int e0 = g_rowptr[n];
    int e1 = g_rowptr[n + 1];     // padded even length

    unsigned long long a0 = 0ull, a1 = 0ull;
    #pragma unroll 4
    for (int e = e0 + half; e < e1; e += 2) {
        int2 ec = g_csr[e];
        float c = __int_as_float(ec.y);             // dinv[src]
        float4 v = ((const float4*)h)[(size_t)ec.x * 16 + fl];
        unsigned long long cc = pack2(c, c);
        ffma2(a0, cc, pack2(v.x, v.y));
        ffma2(a1, cc, pack2(v.z, v.w));
    }
    float2 f0 = unpack2(a0), f1 = unpack2(a1);
    float4 acc = make_float4(f0.x, f0.y, f1.x, f1.y);
    acc.x += __shfl_xor_sync(0xffffffffu, acc.x, 16);
    acc.y += __shfl_xor_sync(0xffffffffu, acc.y, 16);
    acc.z += __shfl_xor_sync(0xffffffffu, acc.z, 16);
    acc.w += __shfl_xor_sync(0xffffffffu, acc.w, 16);

    // scale by dinv[n], add self-loop + bias, store (half 0 owns the row)
    float di = g_dinv[n];
    float cs = di * di;
    if (half == 0) {
        float4 hv = ((const float4*)h)[(size_t)n * 16 + fl];
        float4 bv = ((const float4*)bias)[fl];
        acc.x = fmaf(di, acc.x, fmaf(cs, hv.x, bv.x));
        acc.y = fmaf(di, acc.y, fmaf(cs, hv.y, bv.y));
        acc.z = fmaf(di, acc.z, fmaf(cs, hv.z, bv.z));
        acc.w = fmaf(di, acc.w, fmaf(cs, hv.w, bv.w));
        ((float4*)dstbuf)[(size_t)n * 16 + fl] = acc;

        if (MODE == 1) {
            int g = batch[n];
            if (fl == 0) atomicAdd(&g_cnt[g], 1.0f);
            atomicAdd(((float4*)g_pool) + (size_t)g * 16 + fl, acc);
        }
    }
}

// ---------------- BN statistics: one streaming pass over g_agg ----------------
__global__ void bnstats_kernel() {
    int tid    = blockIdx.x * blockDim.x + threadIdx.x;
    int stride = gridDim.x * blockDim.x;
    float sum = 0.f, sq = 0.f;
    for (int idx = tid; idx < NN * D; idx += stride) {
        float v = g_agg[idx];
        sum += v; sq += v * v;
    }
    __shared__ float s_sum[256], s_sq[256];
    s_sum[threadIdx.x] = sum; s_sq[threadIdx.x] = sq;
    __syncthreads();
    if (threadIdx.x < 64) {
        float ts = s_sum[threadIdx.x] + s_sum[threadIdx.x + 64] +
                   s_sum[threadIdx.x + 128] + s_sum[threadIdx.x + 192];
        float tq = s_sq[threadIdx.x] + s_sq[threadIdx.x + 64] +
                   s_sq[threadIdx.x + 128] + s_sq[threadIdx.x + 192];
        atomicAdd(&g_bnsum[threadIdx.x], ts);
        atomicAdd(&g_bnsq [threadIdx.x], tq);
    }
}

__global__ void pool_div_kernel(float* __restrict__ rep) {
    int t = blockIdx.x * blockDim.x + threadIdx.x;
    if (t >= GG * D) return;
    int g = t >> 6;
    rep[t] = g_pool[t] / fmaxf(g_cnt[g], 1.0f);
}

// ---------------- side stream for capture-time fork/join ----------------
struct SideCtx {
    cudaStream_t s2;
    cudaEvent_t evFork, evJoin;
    SideCtx() {
        cudaStreamCreateWithFlags(&s2, cudaStreamNonBlocking);
        cudaEventCreateWithFlags(&evFork, cudaEventDisableTiming);
        cudaEventCreateWithFlags(&evJoin, cudaEventDisableTiming);
    }
};
static SideCtx g_side;

// ---------------- launch ----------------
extern "C" void kernel_launch(void* const* d_in, const int* in_sizes, int n_in,
                              void* d_out, int out_size) {
    const float* x     = (const float*)d_in[0];
    const int*   ei    = (const int*)  d_in[1];
    const int*   batch = (const int*)  d_in[2];
    const float* W1    = (const float*)d_in[3];
    const float* b1    = (const float*)d_in[4];
    const float* gamma = (const float*)d_in[5];
    const float* beta  = (const float*)d_in[6];
    const float* W2    = (const float*)d_in[7];
    const float* b2    = (const float*)d_in[8];
    float* out = (float*)d_out;
    const int* src = ei;
    const int* dst = ei + EE;

    const int TPB = 256;
    int e4_blocks   = (EE / 4 + TPB - 1) / TPB;        // 782
    int gemm_blocks = (NN + 63) / 64;                  // 782
    int agg_blocks  = NN / 8;                          // 6250 (warp per node)

    // Fork: zero + GEMM-1 run concurrently with the CSR build.
    cudaEventRecord(g_side.evFork, 0);
    cudaStreamWaitEvent(g_side.s2, g_side.evFork, 0);
    zero_kernel<<<16, TPB, 0, g_side.s2>>>();
    gemm64_kernel<0><<<gemm_blocks, dim3(16, 16), 0, g_side.s2>>>(x, W1, gamma, beta);
    cudaEventRecord(g_side.evJoin, g_side.s2);

    // Main branch: CSR build (g_degi is zero on entry — invariant)
    degree_kernel<<<e4_blocks, TPB>>>(dst);
    scan1_kernel<<<SCAN_BLOCKS, 256>>>();
    scan23_kernel<<<SCAN_BLOCKS, 256>>>();
    csr_fill_kernel<<<e4_blocks, TPB>>>(src, dst);

    // Join, then the serial tail
    cudaStreamWaitEvent(0, g_side.evJoin, 0);
    aggregate_kernel<0><<<agg_blocks, TPB>>>(out, b1, batch);
    bnstats_kernel<<<1184, TPB>>>();
    gemm64_kernel<1><<<gemm_blocks, dim3(16, 16)>>>(x, W2, gamma, beta);
    aggregate_kernel<1><<<agg_blocks, TPB>>>(out, b2, batch);
    pool_div_kernel<<<16, TPB>>>(out + (size_t)NN * D);
}

// round 16
// speedup vs baseline: 1.0780x; 1.0059x over previous
#include <cuda_runtime.h>
#include <math.h>

#define NN 50000
#define EE 800000
#define D  64
#define GG 64
#define BN_EPS 1e-5f
#define SCAN_BLOCKS 196   // ceil(50000/256)

// ---------------- device scratch (device-code access only) ----------------
__device__ int   g_degi  [NN];          // zero at load; re-zeroed by scan each call
__device__ float g_dinv  [NN];
__device__ int   g_rowptr[NN + 1];      // padded-exclusive scan + sentinel
__device__ int   g_cursor[NN];
__device__ unsigned long long g_scanstate[SCAN_BLOCKS];  // hi32: 0=inv,1=agg,2=prefix; lo32: value
__device__ __align__(16) int2  g_csr[EE + NN];  // (src, dinv[src] bits), even-padded
__device__ __align__(16) float g_h1 [NN * D];
__device__ __align__(16) float g_agg[NN * D];
__device__ __align__(16) float g_h2 [NN * D];
__device__ float g_bnsum[D];
__device__ float g_bnsq [D];
__device__ __align__(16) float g_pool[GG * D];
__device__ float g_cnt [GG];

// ---------------- packed f32x2 helpers ----------------
__device__ __forceinline__ unsigned long long pack2(float x, float y) {
    unsigned long long r;
    asm("mov.b64 %0, {%1, %2};" : "=l"(r) : "f"(x), "f"(y));
    return r;
}
__device__ __forceinline__ void ffma2(unsigned long long& d,
                                      unsigned long long a, unsigned long long b) {
    asm("fma.rn.f32x2 %0, %1, %2, %0;" : "+l"(d) : "l"(a), "l"(b));
}
__device__ __forceinline__ float2 unpack2(unsigned long long v) {
    float2 f;
    asm("mov.b64 {%0, %1}, %2;" : "=f"(f.x), "=f"(f.y) : "l"(v));
    return f;
}

// ---------------- relaxed 64-bit load/store for the lookback protocol ----------------
__device__ __forceinline__ unsigned long long ldrlx(unsigned long long* p) {
    unsigned long long v;
    asm volatile("ld.relaxed.gpu.u64 %0, [%1];" : "=l"(v) : "l"(p) : "memory");
    return v;
}
__device__ __forceinline__ void strlx(unsigned long long* p, unsigned long long v) {
    asm volatile("st.relaxed.gpu.u64 [%0], %1;" :: "l"(p), "l"(v) : "memory");
}

// ---------------- zero small accumulators (runs on side stream) ----------------
__global__ void zero_kernel() {
    int i = blockIdx.x * blockDim.x + threadIdx.x;
    if (i < GG * D) g_pool[i] = 0.f;
    if (i < D)    { g_bnsum[i] = 0.f; g_bnsq[i] = 0.f; }
    if (i < GG)     g_cnt[i] = 0.f;
}

// ---------------- degree: 4 edges per thread (+ scanstate reset) ----------------
__global__ void degree_kernel(const int* __restrict__ dst) {
    int t = blockIdx.x * blockDim.x + threadIdx.x;
    if (t < SCAN_BLOCKS) g_scanstate[t] = 0ull;   // reset lookback state (same stream)
    if (t * 4 >= EE) return;
    int4 d4 = ((const int4*)dst)[t];
    atomicAdd(&g_degi[d4.x], 1);
    atomicAdd(&g_degi[d4.y], 1);
    atomicAdd(&g_degi[d4.z], 1);
    atomicAdd(&g_degi[d4.w], 1);
}

// ---------------- single-pass scan: decoupled lookback (replaces scan1+scan23) -------
// Per block: local inclusive scan of padded degrees + dinv; publish aggregate;
// warp-parallel lookback for the exclusive prefix; write rowptr/cursor, pad slot,
// degi reset, sentinel. No grid barrier; all 196 blocks co-resident.
__global__ void scan_kernel() {
    __shared__ int s[256];
    __shared__ int s_exc;
    int c = blockIdx.x, t = threadIdx.x;
    int idxg = c * 256 + t;

    int dv = (idxg < NN) ? g_degi[idxg] : 0;
    if (idxg < NN) g_dinv[idxg] = rsqrtf((float)dv + 1.0f);
    int vp = (dv + 1) & ~1;                       // pad degree to even
    s[t] = vp;
    __syncthreads();
    for (int o = 1; o < 256; o <<= 1) {           // inclusive scan
        int a = (t >= o) ? s[t - o] : 0;
        __syncthreads();
        s[t] += a;
        __syncthreads();
    }
    int total = s[255];

    if (t < 32) {
        if (c == 0) {
            if (t == 0) {
                strlx(&g_scanstate[0], (2ull << 32) | (unsigned)total);
                s_exc = 0;
            }
        } else {
            if (t == 0) strlx(&g_scanstate[c], (1ull << 32) | (unsigned)total);
            // warp-parallel lookback, window of 32 predecessors per iteration
            long long exc = 0;
            int base = c - 1;
            int done = 0;
            while (!done) {
                int j = base - t;                 // lane 0 = nearest predecessor
                unsigned long long st = (j >= 0) ? ldrlx(&g_scanstate[j]) : (2ull << 32);
                unsigned flag = (unsigned)(st >> 32);
                if (__ballot_sync(0xffffffffu, flag >= 1u) != 0xffffffffu) continue;
                unsigned pmask = __ballot_sync(0xffffffffu, flag == 2u);
                int plane = __ffs(pmask) - 1;     // nearest block with known prefix (-1: none)
                long long val = (long long)(st & 0xffffffffull);
                long long contrib = (plane >= 0) ? ((t <= plane) ? val : 0) : val;
                #pragma unroll
                for (int o = 16; o > 0; o >>= 1)
                    contrib += __shfl_down_sync(0xffffffffu, contrib, o);
                contrib = __shfl_sync(0xffffffffu, contrib, 0);
                exc += contrib;
                if (plane >= 0) done = 1; else base -= 32;
            }
            if (t == 0) {
                strlx(&g_scanstate[c], (2ull << 32) | (unsigned)(exc + total));
                s_exc = (int)exc;
            }
        }
    }
    __syncthreads();

    int blockoff = s_exc;
    if (idxg < NN) {
        int rp = blockoff + s[t] - vp;            // exclusive padded offset
        g_rowptr[idxg] = rp;
        g_cursor[idxg] = rp;
        if (dv & 1) g_csr[rp + dv] = make_int2(0, 0);  // zero pad entry
        g_degi[idxg] = 0;                              // invariant for next call
        if (idxg == NN - 1) g_rowptr[NN] = blockoff + s[t];
    }
}

// ---------------- CSR fill: 4 edges/thread, stores (src, dinv[src]) ----------------
__global__ void csr_fill_kernel(const int* __restrict__ src,
                                const int* __restrict__ dst) {
    int t = blockIdx.x * blockDim.x + threadIdx.x;
    if (t * 4 >= EE) return;
    int4 s4 = ((const int4*)src)[t];
    int4 d4 = ((const int4*)dst)[t];
    int p0 = atomicAdd(&g_cursor[d4.x], 1);
    int p1 = atomicAdd(&g_cursor[d4.y], 1);
    int p2 = atomicAdd(&g_cursor[d4.z], 1);
    int p3 = atomicAdd(&g_cursor[d4.w], 1);
    g_csr[p0] = make_int2(s4.x, __float_as_int(g_dinv[s4.x]));
    g_csr[p1] = make_int2(s4.y, __float_as_int(g_dinv[s4.y]));
    g_csr[p2] = make_int2(s4.z, __float_as_int(g_dinv[s4.z]));
    g_csr[p3] = make_int2(s4.w, __float_as_int(g_dinv[s4.w]));
}

// ---------------- GEMM: 256 threads, 4x4 outputs/thread, scalar FFMA ----------------
template<int MODE>
__global__ void gemm64_kernel(const float* __restrict__ Xp,
                              const float* __restrict__ W,
                              const float* __restrict__ gamma,
                              const float* __restrict__ beta) {
    const float* __restrict__ X = (MODE == 0) ? Xp : (const float*)g_agg;
    float* __restrict__       Y = (MODE == 0) ? g_h1 : g_h2;

    __shared__ float sX[64][65];
    __shared__ __align__(16) float sW[64][64];
    __shared__ float s_scale[64], s_shift[64];

    int tid  = threadIdx.y * 16 + threadIdx.x;
    int row0 = blockIdx.x * 64;

    if (MODE == 1) {
        if (tid < 64) {
            float inv_n = 1.0f / (float)NN;
            float mu  = g_bnsum[tid] * inv_n;
            float var = g_bnsq[tid] * inv_n - mu * mu;
            float sc  = gamma[tid] * rsqrtf(var + BN_EPS);
            s_scale[tid] = sc;
            s_shift[tid] = beta[tid] - mu * sc;
        }
        __syncthreads();
    }

    #pragma unroll
    for (int t = tid * 4; t < 4096; t += 1024) {
        *(float4*)(&sW[t >> 6][t & 63]) = *(const float4*)(W + t);
    }
    #pragma unroll
    for (int t = tid * 4; t < 4096; t += 1024) {
        int r = t >> 6, c = t & 63;
        float4 v = make_float4(0.f, 0.f, 0.f, 0.f);
        if (row0 + r < NN) v = *(const float4*)(X + (size_t)(row0 + r) * D + c);
        if (MODE == 1) {
            v.x = v.x * s_scale[c]     + s_shift[c];
            v.y = v.y * s_scale[c + 1] + s_shift[c + 1];
            v.z = v.z * s_scale[c + 2] + s_shift[c + 2];
            v.w = v.w * s_scale[c + 3] + s_shift[c + 3];
            v.x = (v.x > 0.f) ? v.x : (__expf(v.x) - 1.0f);
            v.y = (v.y > 0.f) ? v.y : (__expf(v.y) - 1.0f);
            v.z = (v.z > 0.f) ? v.z : (__expf(v.z) - 1.0f);
            v.w = (v.w > 0.f) ? v.w : (__expf(v.w) - 1.0f);
        }
        sX[r][c] = v.x; sX[r][c + 1] = v.y; sX[r][c + 2] = v.z; sX[r][c + 3] = v.w;
    }
    __syncthreads();

    float acc[4][4] = {};
    int c0 = threadIdx.x * 4, r0 = threadIdx.y * 4;
    #pragma unroll 16
    for (int k = 0; k < 64; k++) {
        float4 w = *(const float4*)(&sW[k][c0]);
        #pragma unroll
        for (int r = 0; r < 4; r++) {
            float xv = sX[r0 + r][k];
            acc[r][0] += xv * w.x; acc[r][1] += xv * w.y;
            acc[r][2] += xv * w.z; acc[r][3] += xv * w.w;
        }
    }
    #pragma unroll
    for (int r = 0; r < 4; r++) {
        int row = row0 + r0 + r;
        if (row < NN)
            *(float4*)(Y + (size_t)row * D + c0) =
                make_float4(acc[r][0], acc[r][1], acc[r][2], acc[r][3]);
    }
}

// ---------------- gather aggregation: warp/node, half-warps (R8 proven layout) -------
// CSR stores dinv[src]; final scale by dinv[n]. NO atomics/syncthreads in MODE 0.
template<int MODE>
__global__ void aggregate_kernel(float* __restrict__ outp,
                                 const float* __restrict__ bias,
                                 const int* __restrict__ batch) {
    const float* __restrict__ h = (MODE == 0) ? g_h1 : g_h2;
    float* __restrict__ dstbuf  = (MODE == 0) ? g_agg : outp;

    int n    = (blockIdx.x * blockDim.x + threadIdx.x) >> 5;  // grid: n < NN
    int lane = threadIdx.x & 31;
    int half = lane >> 4;
    int fl   = lane & 15;

    int e0 = g_rowptr[n];
    int e1 = g_rowptr[n + 1];     // padded even length

    unsigned long long a0 = 0ull, a1 = 0ull;
    #pragma unroll 4
    for (int e = e0 + half; e < e1; e += 2) {
        int2 ec = g_csr[e];
        float c = __int_as_float(ec.y);             // dinv[src]
        float4 v = ((const float4*)h)[(size_t)ec.x * 16 + fl];
        unsigned long long cc = pack2(c, c);
        ffma2(a0, cc, pack2(v.x, v.y));
        ffma2(a1, cc, pack2(v.z, v.w));
    }
    float2 f0 = unpack2(a0), f1 = unpack2(a1);
    float4 acc = make_float4(f0.x, f0.y, f1.x, f1.y);
    acc.x += __shfl_xor_sync(0xffffffffu, acc.x, 16);
    acc.y += __shfl_xor_sync(0xffffffffu, acc.y, 16);
    acc.z += __shfl_xor_sync(0xffffffffu, acc.z, 16);
    acc.w += __shfl_xor_sync(0xffffffffu, acc.w, 16);

    // scale by dinv[n], add self-loop + bias, store (half 0 owns the row)
    float di = g_dinv[n];
    float cs = di * di;
    if (half == 0) {
        float4 hv = ((const float4*)h)[(size_t)n * 16 + fl];
        float4 bv = ((const float4*)bias)[fl];
        acc.x = fmaf(di, acc.x, fmaf(cs, hv.x, bv.x));
        acc.y = fmaf(di, acc.y, fmaf(cs, hv.y, bv.y));
        acc.z = fmaf(di, acc.z, fmaf(cs, hv.z, bv.z));
        acc.w = fmaf(di, acc.w, fmaf(cs, hv.w, bv.w));
        ((float4*)dstbuf)[(size_t)n * 16 + fl] = acc;

        if (MODE == 1) {
            int g = batch[n];
            if (fl == 0) atomicAdd(&g_cnt[g], 1.0f);
            atomicAdd(((float4*)g_pool) + (size_t)g * 16 + fl, acc);
        }
    }
}

// ---------------- BN statistics: one streaming pass over g_agg ----------------
__global__ void bnstats_kernel() {
    int tid    = blockIdx.x * blockDim.x + threadIdx.x;
    int stride = gridDim.x * blockDim.x;
    float sum = 0.f, sq = 0.f;
    for (int idx = tid; idx < NN * D; idx += stride) {
        float v = g_agg[idx];
        sum += v; sq += v * v;
    }
    __shared__ float s_sum[256], s_sq[256];
    s_sum[threadIdx.x] = sum; s_sq[threadIdx.x] = sq;
    __syncthreads();
    if (threadIdx.x < 64) {
        float ts = s_sum[threadIdx.x] + s_sum[threadIdx.x + 64] +
                   s_sum[threadIdx.x + 128] + s_sum[threadIdx.x + 192];
        float tq = s_sq[threadIdx.x] + s_sq[threadIdx.x + 64] +
                   s_sq[threadIdx.x + 128] + s_sq[threadIdx.x + 192];
        atomicAdd(&g_bnsum[threadIdx.x], ts);
        atomicAdd(&g_bnsq [threadIdx.x], tq);
    }
}

__global__ void pool_div_kernel(float* __restrict__ rep) {
    int t = blockIdx.x * blockDim.x + threadIdx.x;
    if (t >= GG * D) return;
    int g = t >> 6;
    rep[t] = g_pool[t] / fmaxf(g_cnt[g], 1.0f);
}

// ---------------- side stream for capture-time fork/join ----------------
struct SideCtx {
    cudaStream_t s2;
    cudaEvent_t evFork, evJoin;
    SideCtx() {
        cudaStreamCreateWithFlags(&s2, cudaStreamNonBlocking);
        cudaEventCreateWithFlags(&evFork, cudaEventDisableTiming);
        cudaEventCreateWithFlags(&evJoin, cudaEventDisableTiming);
    }
};
static SideCtx g_side;

// ---------------- launch ----------------
extern "C" void kernel_launch(void* const* d_in, const int* in_sizes, int n_in,
                              void* d_out, int out_size) {
    const float* x     = (const float*)d_in[0];
    const int*   ei    = (const int*)  d_in[1];
    const int*   batch = (const int*)  d_in[2];
    const float* W1    = (const float*)d_in[3];
    const float* b1    = (const float*)d_in[4];
    const float* gamma = (const float*)d_in[5];
    const float* beta  = (const float*)d_in[6];
    const float* W2    = (const float*)d_in[7];
    const float* b2    = (const float*)d_in[8];
    float* out = (float*)d_out;
    const int* src = ei;
    const int* dst = ei + EE;

    const int TPB = 256;
    int e4_blocks   = (EE / 4 + TPB - 1) / TPB;        // 782
    int gemm_blocks = (NN + 63) / 64;                  // 782
    int agg_blocks  = NN / 8;                          // 6250 (warp per node)

    // Fork: zero + GEMM-1 run concurrently with the CSR build.
    cudaEventRecord(g_side.evFork, 0);
    cudaStreamWaitEvent(g_side.s2, g_side.evFork, 0);
    zero_kernel<<<16, TPB, 0, g_side.s2>>>();
    gemm64_kernel<0><<<gemm_blocks, dim3(16, 16), 0, g_side.s2>>>(x, W1, gamma, beta);
    cudaEventRecord(g_side.evJoin, g_side.s2);

    // Main branch: CSR build (g_degi is zero on entry — invariant)
    degree_kernel<<<e4_blocks, TPB>>>(dst);
    scan_kernel<<<SCAN_BLOCKS, 256>>>();               // single-pass decoupled lookback
    csr_fill_kernel<<<e4_blocks, TPB>>>(src, dst);

    // Join, then the serial tail
    cudaStreamWaitEvent(0, g_side.evJoin, 0);
    aggregate_kernel<0><<<agg_blocks, TPB>>>(out, b1, batch);
    bnstats_kernel<<<1184, TPB>>>();
    gemm64_kernel<1><<<gemm_blocks, dim3(16, 16)>>>(x, W2, gamma, beta);
    aggregate_kernel<1><<<agg_blocks, TPB>>>(out, b2, batch);
    pool_div_kernel<<<16, TPB>>>(out + (size_t)NN * D);
}

// round 17
// speedup vs baseline: 1.0802x; 1.0020x over previous
#include <cuda_runtime.h>
#include <math.h>

#define NN 50000
#define EE 800000
#define D  64
#define GG 64
#define BN_EPS 1e-5f
#define SCAN_BLOCKS 196   // ceil(50000/256)

// ---------------- device scratch (device-code access only) ----------------
__device__ int   g_degi  [NN];          // zero at load; re-zeroed by scan each call
__device__ float g_dinv  [NN];
__device__ int   g_rowptr[NN + 1];      // padded-exclusive scan + sentinel
__device__ int   g_cursor[NN];
__device__ unsigned long long g_scanstate[SCAN_BLOCKS];  // hi32: 0=inv,1=agg,2=prefix; lo32: value
__device__ __align__(16) int2  g_csr[EE + NN];  // (src, dinv[src] bits), even-padded
__device__ __align__(16) float g_h1 [NN * D];
__device__ __align__(16) float g_agg[NN * D];
__device__ __align__(16) float g_h2 [NN * D];
__device__ float g_bnsum[D];
__device__ float g_bnsq [D];
__device__ __align__(16) float g_pool[GG * D];
__device__ float g_cnt [GG];

// ---------------- packed f32x2 helpers ----------------
__device__ __forceinline__ unsigned long long pack2(float x, float y) {
    unsigned long long r;
    asm("mov.b64 %0, {%1, %2};" : "=l"(r) : "f"(x), "f"(y));
    return r;
}
__device__ __forceinline__ void ffma2(unsigned long long& d,
                                      unsigned long long a, unsigned long long b) {
    asm("fma.rn.f32x2 %0, %1, %2, %0;" : "+l"(d) : "l"(a), "l"(b));
}
__device__ __forceinline__ float2 unpack2(unsigned long long v) {
    float2 f;
    asm("mov.b64 {%0, %1}, %2;" : "=f"(f.x), "=f"(f.y) : "l"(v));
    return f;
}

// ---------------- relaxed 64-bit load/store for the lookback protocol ----------------
__device__ __forceinline__ unsigned long long ldrlx(unsigned long long* p) {
    unsigned long long v;
    asm volatile("ld.relaxed.gpu.u64 %0, [%1];" : "=l"(v) : "l"(p) : "memory");
    return v;
}
__device__ __forceinline__ void strlx(unsigned long long* p, unsigned long long v) {
    asm volatile("st.relaxed.gpu.u64 [%0], %1;" :: "l"(p), "l"(v) : "memory");
}

// ---------------- zero small accumulators (runs on side stream) ----------------
__global__ void zero_kernel() {
    int i = blockIdx.x * blockDim.x + threadIdx.x;
    if (i < GG * D) g_pool[i] = 0.f;
    if (i < D)    { g_bnsum[i] = 0.f; g_bnsq[i] = 0.f; }
    if (i < GG)     g_cnt[i] = 0.f;
}

// ---------------- degree: 4 edges per thread (+ scanstate reset) ----------------
__global__ void degree_kernel(const int* __restrict__ dst) {
    int t = blockIdx.x * blockDim.x + threadIdx.x;
    if (t < SCAN_BLOCKS) g_scanstate[t] = 0ull;   // reset lookback state (same stream)
    if (t * 4 >= EE) return;
    int4 d4 = ((const int4*)dst)[t];
    atomicAdd(&g_degi[d4.x], 1);
    atomicAdd(&g_degi[d4.y], 1);
    atomicAdd(&g_degi[d4.z], 1);
    atomicAdd(&g_degi[d4.w], 1);
}

// ---------------- single-pass scan: shuffle local scan + decoupled lookback ----------
// Local inclusive scan via warp shuffles (2 __syncthreads total, was 32), then
// warp-parallel lookback for the exclusive block prefix. No grid barrier.
__global__ void scan_kernel() {
    __shared__ int wsum[8];
    __shared__ int s_exc;
    int c = blockIdx.x, t = threadIdx.x;
    int lane = t & 31, wid = t >> 5;
    int idxg = c * 256 + t;

    int dv = (idxg < NN) ? g_degi[idxg] : 0;
    if (idxg < NN) g_dinv[idxg] = rsqrtf((float)dv + 1.0f);
    int vp = (dv + 1) & ~1;                       // pad degree to even

    // warp-level inclusive scan (no barriers)
    int v = vp;
    #pragma unroll
    for (int o = 1; o < 32; o <<= 1) {
        int nv = __shfl_up_sync(0xffffffffu, v, o);
        if (lane >= o) v += nv;
    }
    if (lane == 31) wsum[wid] = v;
    __syncthreads();
    if (t < 8) {                                  // scan the 8 warp sums
        int w = wsum[t];
        #pragma unroll
        for (int o = 1; o < 8; o <<= 1) {
            int nw = __shfl_up_sync(0xffu, w, o);
            if (t >= o) w += nw;
        }
        wsum[t] = w;
    }
    __syncthreads();
    int incl  = v + ((wid > 0) ? wsum[wid - 1] : 0);   // block-local inclusive
    int total = wsum[7];

    if (t < 32) {
        if (c == 0) {
            if (t == 0) {
                strlx(&g_scanstate[0], (2ull << 32) | (unsigned)total);
                s_exc = 0;
            }
        } else {
            if (t == 0) strlx(&g_scanstate[c], (1ull << 32) | (unsigned)total);
            // warp-parallel lookback, window of 32 predecessors per iteration
            long long exc = 0;
            int base = c - 1;
            int done = 0;
            while (!done) {
                int j = base - t;                 // lane 0 = nearest predecessor
                unsigned long long st = (j >= 0) ? ldrlx(&g_scanstate[j]) : (2ull << 32);
                unsigned flag = (unsigned)(st >> 32);
                if (__ballot_sync(0xffffffffu, flag >= 1u) != 0xffffffffu) continue;
                unsigned pmask = __ballot_sync(0xffffffffu, flag == 2u);
                int plane = __ffs(pmask) - 1;     // nearest block with known prefix (-1: none)
                long long val = (long long)(st & 0xffffffffull);
                long long contrib = (plane >= 0) ? ((t <= plane) ? val : 0) : val;
                #pragma unroll
                for (int o = 16; o > 0; o >>= 1)
                    contrib += __shfl_down_sync(0xffffffffu, contrib, o);
                contrib = __shfl_sync(0xffffffffu, contrib, 0);
                exc += contrib;
                if (plane >= 0) done = 1; else base -= 32;
            }
            if (t == 0) {
                strlx(&g_scanstate[c], (2ull << 32) | (unsigned)(exc + total));
                s_exc = (int)exc;
            }
        }
    }
    __syncthreads();

    int blockoff = s_exc;
    if (idxg < NN) {
        int rp = blockoff + incl - vp;            // exclusive padded offset
        g_rowptr[idxg] = rp;
        g_cursor[idxg] = rp;
        if (dv & 1) g_csr[rp + dv] = make_int2(0, 0);  // zero pad entry
        g_degi[idxg] = 0;                              // invariant for next call
        if (idxg == NN - 1) g_rowptr[NN] = blockoff + incl;
    }
}

// ---------------- CSR fill: 4 edges/thread, stores (src, dinv[src]) ----------------
__global__ void csr_fill_kernel(const int* __restrict__ src,
                                const int* __restrict__ dst) {
    int t = blockIdx.x * blockDim.x + threadIdx.x;
    if (t * 4 >= EE) return;
    int4 s4 = ((const int4*)src)[t];
    int4 d4 = ((const int4*)dst)[t];
    int p0 = atomicAdd(&g_cursor[d4.x], 1);
    int p1 = atomicAdd(&g_cursor[d4.y], 1);
    int p2 = atomicAdd(&g_cursor[d4.z], 1);
    int p3 = atomicAdd(&g_cursor[d4.w], 1);
    g_csr[p0] = make_int2(s4.x, __float_as_int(g_dinv[s4.x]));
    g_csr[p1] = make_int2(s4.y, __float_as_int(g_dinv[s4.y]));
    g_csr[p2] = make_int2(s4.z, __float_as_int(g_dinv[s4.z]));
    g_csr[p3] = make_int2(s4.w, __float_as_int(g_dinv[s4.w]));
}

// ---------------- GEMM: 256 threads, 4x4 outputs/thread, scalar FFMA ----------------
template<int MODE>
__global__ void gemm64_kernel(const float* __restrict__ Xp,
                              const float* __restrict__ W,
                              const float* __restrict__ gamma,
                              const float* __restrict__ beta) {
    const float* __restrict__ X = (MODE == 0) ? Xp : (const float*)g_agg;
    float* __restrict__       Y = (MODE == 0) ? g_h1 : g_h2;

    __shared__ float sX[64][65];
    __shared__ __align__(16) float sW[64][64];
    __shared__ float s_scale[64], s_shift[64];

    int tid  = threadIdx.y * 16 + threadIdx.x;
    int row0 = blockIdx.x * 64;

    if (MODE == 1) {
        if (tid < 64) {
            float inv_n = 1.0f / (float)NN;
            float mu  = g_bnsum[tid] * inv_n;
            float var = g_bnsq[tid] * inv_n - mu * mu;
            float sc  = gamma[tid] * rsqrtf(var + BN_EPS);
            s_scale[tid] = sc;
            s_shift[tid] = beta[tid] - mu * sc;
        }
        __syncthreads();
    }

    #pragma unroll
    for (int t = tid * 4; t < 4096; t += 1024) {
        *(float4*)(&sW[t >> 6][t & 63]) = *(const float4*)(W + t);
    }
    #pragma unroll
    for (int t = tid * 4; t < 4096; t += 1024) {
        int r = t >> 6, c = t & 63;
        float4 v = make_float4(0.f, 0.f, 0.f, 0.f);
        if (row0 + r < NN) v = *(const float4*)(X + (size_t)(row0 + r) * D + c);
        if (MODE == 1) {
            v.x = v.x * s_scale[c]     + s_shift[c];
            v.y = v.y * s_scale[c + 1] + s_shift[c + 1];
            v.z = v.z * s_scale[c + 2] + s_shift[c + 2];
            v.w = v.w * s_scale[c + 3] + s_shift[c + 3];
            v.x = (v.x > 0.f) ? v.x : (__expf(v.x) - 1.0f);
            v.y = (v.y > 0.f) ? v.y : (__expf(v.y) - 1.0f);
            v.z = (v.z > 0.f) ? v.z : (__expf(v.z) - 1.0f);
            v.w = (v.w > 0.f) ? v.w : (__expf(v.w) - 1.0f);
        }
        sX[r][c] = v.x; sX[r][c + 1] = v.y; sX[r][c + 2] = v.z; sX[r][c + 3] = v.w;
    }
    __syncthreads();

    float acc[4][4] = {};
    int c0 = threadIdx.x * 4, r0 = threadIdx.y * 4;
    #pragma unroll 16
    for (int k = 0; k < 64; k++) {
        float4 w = *(const float4*)(&sW[k][c0]);
        #pragma unroll
        for (int r = 0; r < 4; r++) {
            float xv = sX[r0 + r][k];
            acc[r][0] += xv * w.x; acc[r][1] += xv * w.y;
            acc[r][2] += xv * w.z; acc[r][3] += xv * w.w;
        }
    }
    #pragma unroll
    for (int r = 0; r < 4; r++) {
        int row = row0 + r0 + r;
        if (row < NN)
            *(float4*)(Y + (size_t)row * D + c0) =
                make_float4(acc[r][0], acc[r][1], acc[r][2], acc[r][3]);
    }
}

// ---------------- gather aggregation: warp/node, half-warps (R8 proven layout) -------
// CSR stores dinv[src]; final scale by dinv[n]. NO atomics/syncthreads in MODE 0.
template<int MODE>
__global__ void aggregate_kernel(float* __restrict__ outp,
                                 const float* __restrict__ bias,
                                 const int* __restrict__ batch) {
    const float* __restrict__ h = (MODE == 0) ? g_h1 : g_h2;
    float* __restrict__ dstbuf  = (MODE == 0) ? g_agg : outp;

    int n    = (blockIdx.x * blockDim.x + threadIdx.x) >> 5;  // grid: n < NN
    int lane = threadIdx.x & 31;
    int half = lane >> 4;
    int fl   = lane & 15;

    int e0 = g_rowptr[n];
    int e1 = g_rowptr[n + 1];     // padded even length

    unsigned long long a0 = 0ull, a1 = 0ull;
    #pragma unroll 4
    for (int e = e0 + half; e < e1; e += 2) {
        int2 ec = g_csr[e];
        float c = __int_as_float(ec.y);             // dinv[src]
        float4 v = ((const float4*)h)[(size_t)ec.x * 16 + fl];
        unsigned long long cc = pack2(c, c);
        ffma2(a0, cc, pack2(v.x, v.y));
        ffma2(a1, cc, pack2(v.z, v.w));
    }
    float2 f0 = unpack2(a0), f1 = unpack2(a1);
    float4 acc = make_float4(f0.x, f0.y, f1.x, f1.y);
    acc.x += __shfl_xor_sync(0xffffffffu, acc.x, 16);
    acc.y += __shfl_xor_sync(0xffffffffu, acc.y, 16);
    acc.z += __shfl_xor_sync(0xffffffffu, acc.z, 16);
    acc.w += __shfl_xor_sync(0xffffffffu, acc.w, 16);

    // scale by dinv[n], add self-loop + bias, store (half 0 owns the row)
    float di = g_dinv[n];
    float cs = di * di;
    if (half == 0) {
        float4 hv = ((const float4*)h)[(size_t)n * 16 + fl];
        float4 bv = ((const float4*)bias)[fl];
        acc.x = fmaf(di, acc.x, fmaf(cs, hv.x, bv.x));
        acc.y = fmaf(di, acc.y, fmaf(cs, hv.y, bv.y));
        acc.z = fmaf(di, acc.z, fmaf(cs, hv.z, bv.z));
        acc.w = fmaf(di, acc.w, fmaf(cs, hv.w, bv.w));
        ((float4*)dstbuf)[(size_t)n * 16 + fl] = acc;

        if (MODE == 1) {
            int g = batch[n];
            if (fl == 0) atomicAdd(&g_cnt[g], 1.0f);
            atomicAdd(((float4*)g_pool) + (size_t)g * 16 + fl, acc);
        }
    }
}

// ---------------- BN statistics: one streaming pass over g_agg ----------------
__global__ void bnstats_kernel() {
    int tid    = blockIdx.x * blockDim.x + threadIdx.x;
    int stride = gridDim.x * blockDim.x;
    float sum = 0.f, sq = 0.f;
    for (int idx = tid; idx < NN * D; idx += stride) {
        float v = g_agg[idx];
        sum += v; sq += v * v;
    }
    __shared__ float s_sum[256], s_sq[256];
    s_sum[threadIdx.x] = sum; s_sq[threadIdx.x] = sq;
    __syncthreads();
    if (threadIdx.x < 64) {
        float ts = s_sum[threadIdx.x] + s_sum[threadIdx.x + 64] +
                   s_sum[threadIdx.x + 128] + s_sum[threadIdx.x + 192];
        float tq = s_sq[threadIdx.x] + s_sq[threadIdx.x + 64] +
                   s_sq[threadIdx.x + 128] + s_sq[threadIdx.x + 192];
        atomicAdd(&g_bnsum[threadIdx.x], ts);
        atomicAdd(&g_bnsq [threadIdx.x], tq);
    }
}

__global__ void pool_div_kernel(float* __restrict__ rep) {
    int t = blockIdx.x * blockDim.x + threadIdx.x;
    if (t >= GG * D) return;
    int g = t >> 6;
    rep[t] = g_pool[t] / fmaxf(g_cnt[g], 1.0f);
}

// ---------------- side stream for capture-time fork/join ----------------
struct SideCtx {
    cudaStream_t s2;
    cudaEvent_t evFork, evJoin;
    SideCtx() {
        cudaStreamCreateWithFlags(&s2, cudaStreamNonBlocking);
        cudaEventCreateWithFlags(&evFork, cudaEventDisableTiming);
        cudaEventCreateWithFlags(&evJoin, cudaEventDisableTiming);
    }
};
static SideCtx g_side;

// ---------------- launch ----------------
extern "C" void kernel_launch(void* const* d_in, const int* in_sizes, int n_in,
                              void* d_out, int out_size) {
    const float* x     = (const float*)d_in[0];
    const int*   ei    = (const int*)  d_in[1];
    const int*   batch = (const int*)  d_in[2];
    const float* W1    = (const float*)d_in[3];
    const float* b1    = (const float*)d_in[4];
    const float* gamma = (const float*)d_in[5];
    const float* beta  = (const float*)d_in[6];
    const float* W2    = (const float*)d_in[7];
    const float* b2    = (const float*)d_in[8];
    float* out = (float*)d_out;
    const int* src = ei;
    const int* dst = ei + EE;

    const int TPB = 256;
    int e4_blocks   = (EE / 4 + TPB - 1) / TPB;        // 782
    int gemm_blocks = (NN + 63) / 64;                  // 782
    int agg_blocks  = NN / 8;                          // 6250 (warp per node)

    // Fork: zero + GEMM-1 run concurrently with the CSR build.
    cudaEventRecord(g_side.evFork, 0);
    cudaStreamWaitEvent(g_side.s2, g_side.evFork, 0);
    zero_kernel<<<16, TPB, 0, g_side.s2>>>();
    gemm64_kernel<0><<<gemm_blocks, dim3(16, 16), 0, g_side.s2>>>(x, W1, gamma, beta);
    cudaEventRecord(g_side.evJoin, g_side.s2);

    // Main branch: CSR build (g_degi is zero on entry — invariant)
    degree_kernel<<<e4_blocks, TPB>>>(dst);
    scan_kernel<<<SCAN_BLOCKS, 256>>>();               // shuffle scan + decoupled lookback
    csr_fill_kernel<<<e4_blocks, TPB>>>(src, dst);

    // Join, then the serial tail
    cudaStreamWaitEvent(0, g_side.evJoin, 0);
    aggregate_kernel<0><<<agg_blocks, TPB>>>(out, b1, batch);
    bnstats_kernel<<<1184, TPB>>>();
    gemm64_kernel<1><<<gemm_blocks, dim3(16, 16)>>>(x, W2, gamma, beta);
    aggregate_kernel<1><<<agg_blocks, TPB>>>(out, b2, batch);
    pool_div_kernel<<<16, TPB>>>(out + (size_t)NN * D);
}